// round 10
// baseline (speedup 1.0000x reference)
#include <cuda_runtime.h>
#include <cuda_bf16.h>

#define HID 64
#define NB  32
#define EMAX 500000

typedef unsigned long long ull;

// ---------------- static scratch ----------------
__device__ float g_W[(size_t)EMAX * 128];   // per-edge weights: [e][m*64 + j]
__device__ float g_H[(size_t)EMAX * 128];   // hidden activations: [e][m*64 + k]

// ---------------- packed fp32x2 helpers ----------------
__device__ __forceinline__ ull dup2(float a) {
    ull r; asm("mov.b64 %0,{%1,%1};" : "=l"(r) : "f"(a)); return r;
}
__device__ __forceinline__ void up2(ull v, float& a, float& b) {
    asm("mov.b64 {%0,%1},%2;" : "=f"(a), "=f"(b) : "l"(v));
}
__device__ __forceinline__ void fma2(ull& d, ull a, ull b) {
    asm("fma.rn.f32x2 %0,%1,%2,%0;" : "+l"(d) : "l"(a), "l"(b));
}
__device__ __forceinline__ void red4(float* p, float a, float b, float c, float d) {
    asm volatile("red.global.add.v4.f32 [%0],{%1,%2,%3,%4};"
                 :: "l"(p), "f"(a), "f"(b), "f"(c), "f"(d) : "memory");
}
__device__ __forceinline__ float silu_f(float y) {
    return __fdividef(y, 1.f + __expf(-y));
}

// ================= L1: x @ w1 -> silu -> g_H (both m) =================
__global__ void __launch_bounds__(128) l1_kernel(
    const float* __restrict__ elen,
    const float* __restrict__ sw1, const float* __restrict__ sb1,
    const float* __restrict__ vw1, const float* __restrict__ vb1,
    int E)
{
    __shared__ float sw[2 * NB * HID + 2 * HID];   // 4096 + 128 floats = 16.5 KB
    int t = threadIdx.x;
    {
        const float4* g0 = (const float4*)sw1;
        const float4* g1 = (const float4*)vw1;
        float4* d = (float4*)sw;
        #pragma unroll
        for (int i = 0; i < 4; i++) {
            d[i * 128 + t]       = g0[i * 128 + t];
            d[512 + i * 128 + t] = g1[i * 128 + t];
        }
        if (t < HID) {
            sw[4096 + t]       = sb1[t];
            sw[4096 + HID + t] = vb1[t];
        }
    }
    __syncthreads();

    long long e0 = (long long)blockIdx.x * 256 + t;
    long long e1 = e0 + 128;
    bool v0 = (e0 < E), v1 = (e1 < E);
    const float* x0 = elen + (v0 ? e0 : 0) * NB;
    const float* x1 = elen + (v1 ? e1 : 0) * NB;

    #pragma unroll 1
    for (int m = 0; m < 2; m++) {
        const float* w = sw + m * (NB * HID);
        const ull* bp = (const ull*)(sw + 4096 + m * HID);
        #pragma unroll 1
        for (int jt = 0; jt < 2; jt++) {
            int j0 = jt * 32;
            ull A0[16], A1[16];
            #pragma unroll
            for (int q = 0; q < 16; q++) {
                ull b = bp[j0 / 2 + q]; A0[q] = b; A1[q] = b;
            }
            #pragma unroll 1
            for (int k0 = 0; k0 < NB; k0 += 4) {
                float4 xv0 = *(const float4*)(x0 + k0);
                float4 xv1 = *(const float4*)(x1 + k0);
                float s0[4] = {xv0.x, xv0.y, xv0.z, xv0.w};
                float s1[4] = {xv1.x, xv1.y, xv1.z, xv1.w};
                #pragma unroll
                for (int s = 0; s < 4; s++) {
                    ull xd0 = dup2(s0[s]), xd1 = dup2(s1[s]);
                    const ulonglong2* wp =
                        (const ulonglong2*)(w + (k0 + s) * HID + j0);
                    #pragma unroll
                    for (int q = 0; q < 8; q++) {
                        ulonglong2 wv = wp[q];
                        fma2(A0[2 * q],     xd0, wv.x);
                        fma2(A0[2 * q + 1], xd0, wv.y);
                        fma2(A1[2 * q],     xd1, wv.x);
                        fma2(A1[2 * q + 1], xd1, wv.y);
                    }
                }
            }
            if (v0) {
                float4* o = (float4*)(g_H + (size_t)e0 * 128 + m * 64 + j0);
                #pragma unroll
                for (int i = 0; i < 8; i++) {
                    float a, b, c, d;
                    up2(A0[2 * i], a, b); up2(A0[2 * i + 1], c, d);
                    o[i] = make_float4(silu_f(a), silu_f(b), silu_f(c), silu_f(d));
                }
            }
            if (v1) {
                float4* o = (float4*)(g_H + (size_t)e1 * 128 + m * 64 + j0);
                #pragma unroll
                for (int i = 0; i < 8; i++) {
                    float a, b, c, d;
                    up2(A1[2 * i], a, b); up2(A1[2 * i + 1], c, d);
                    o[i] = make_float4(silu_f(a), silu_f(b), silu_f(c), silu_f(d));
                }
            }
        }
    }
}

// ================= L2: g_H @ w2 -> g_W (both m) =================
__global__ void __launch_bounds__(128) l2_kernel(
    const float* __restrict__ sw2, const float* __restrict__ sb2,
    const float* __restrict__ vw2, const float* __restrict__ vb2,
    int E)
{
    __shared__ float sw[2 * HID * HID + 2 * HID];  // 8192 + 128 floats = 33 KB
    int t = threadIdx.x;
    {
        const float4* g0 = (const float4*)sw2;
        const float4* g1 = (const float4*)vw2;
        float4* d = (float4*)sw;
        #pragma unroll
        for (int i = 0; i < 8; i++) {
            d[i * 128 + t]        = g0[i * 128 + t];
            d[1024 + i * 128 + t] = g1[i * 128 + t];
        }
        if (t < HID) {
            sw[8192 + t]       = sb2[t];
            sw[8192 + HID + t] = vb2[t];
        }
    }
    __syncthreads();

    long long e0 = (long long)blockIdx.x * 256 + t;
    long long e1 = e0 + 128;
    bool v0 = (e0 < E), v1 = (e1 < E);
    const float* h0p = g_H + (size_t)(v0 ? e0 : 0) * 128;
    const float* h1p = g_H + (size_t)(v1 ? e1 : 0) * 128;

    #pragma unroll 1
    for (int m = 0; m < 2; m++) {
        const float* w = sw + m * (HID * HID);
        const ull* bp = (const ull*)(sw + 8192 + m * HID);
        #pragma unroll 1
        for (int jt = 0; jt < 2; jt++) {
            int j0 = jt * 32;
            ull A0[16], A1[16];
            #pragma unroll
            for (int q = 0; q < 16; q++) {
                ull b = bp[j0 / 2 + q]; A0[q] = b; A1[q] = b;
            }
            #pragma unroll 1
            for (int k0 = 0; k0 < HID; k0 += 4) {
                float4 hv0 = *(const float4*)(h0p + m * 64 + k0);
                float4 hv1 = *(const float4*)(h1p + m * 64 + k0);
                float s0[4] = {hv0.x, hv0.y, hv0.z, hv0.w};
                float s1[4] = {hv1.x, hv1.y, hv1.z, hv1.w};
                #pragma unroll
                for (int s = 0; s < 4; s++) {
                    ull hd0 = dup2(s0[s]), hd1 = dup2(s1[s]);
                    const ulonglong2* wp =
                        (const ulonglong2*)(w + (k0 + s) * HID + j0);
                    #pragma unroll
                    for (int q = 0; q < 8; q++) {
                        ulonglong2 wv = wp[q];
                        fma2(A0[2 * q],     hd0, wv.x);
                        fma2(A0[2 * q + 1], hd0, wv.y);
                        fma2(A1[2 * q],     hd1, wv.x);
                        fma2(A1[2 * q + 1], hd1, wv.y);
                    }
                }
            }
            if (v0) {
                float4* o = (float4*)(g_W + (size_t)e0 * 128 + m * 64 + j0);
                #pragma unroll
                for (int i = 0; i < 8; i++) {
                    float a, b, c, d;
                    up2(A0[2 * i], a, b); up2(A0[2 * i + 1], c, d);
                    o[i] = make_float4(a, b, c, d);
                }
            }
            if (v1) {
                float4* o = (float4*)(g_W + (size_t)e1 * 128 + m * 64 + j0);
                #pragma unroll
                for (int i = 0; i < 8; i++) {
                    float a, b, c, d;
                    up2(A1[2 * i], a, b); up2(A1[2 * i + 1], c, d);
                    o[i] = make_float4(a, b, c, d);
                }
            }
        }
    }
}

// ================= K2: one warp per edge, coalesced gather + red4 scatter =================
__global__ void __launch_bounds__(256) scatter_kernel(
    const float* __restrict__ scalar, const float* __restrict__ vec,
    const int* __restrict__ eidx,
    float* __restrict__ out, int E, long long nscal)
{
    long long e = (long long)blockIdx.x * 8 + (threadIdx.x >> 5);
    if (e >= E) return;
    int lane = threadIdx.x & 31;
    int seg = lane >> 3;               // 0: scalar, 1..3: vector dim
    int j = (lane * 8) & 63;           // 8-column group within seg

    int row = eidx[e];
    int col = eidx[E + e];

    const float* w = g_W + (size_t)e * 128 + (seg ? 64 : 0) + j;
    const float* s = (seg == 0)
        ? scalar + (size_t)col * HID + j
        : vec + (size_t)col * 3 * HID + (seg - 1) * HID + j;
    float* dst = (seg == 0)
        ? out + (size_t)row * HID + j
        : out + nscal + (size_t)row * 3 * HID + (seg - 1) * HID + j;

    float4 w0 = *(const float4*)w;
    float4 w1 = *(const float4*)(w + 4);
    float4 s0 = *(const float4*)s;
    float4 s1 = *(const float4*)(s + 4);

    red4(dst,     s0.x * w0.x, s0.y * w0.y, s0.z * w0.z, s0.w * w0.w);
    red4(dst + 4, s1.x * w1.x, s1.y * w1.y, s1.z * w1.z, s1.w * w1.w);
}

// ================= launch =================
extern "C" void kernel_launch(void* const* d_in, const int* in_sizes, int n_in,
                              void* d_out, int out_size)
{
    const float* scalar = (const float*)d_in[0];
    const float* vec    = (const float*)d_in[1];
    // d_in[2] = edge_sh (unused)
    const float* elen   = (const float*)d_in[3];
    const int*   eidx   = (const int*)d_in[4];
    const float* sw1 = (const float*)d_in[5];
    const float* sb1 = (const float*)d_in[6];
    const float* sw2 = (const float*)d_in[7];
    const float* sb2 = (const float*)d_in[8];
    const float* vw1 = (const float*)d_in[9];
    const float* vb1 = (const float*)d_in[10];
    const float* vw2 = (const float*)d_in[11];
    const float* vb2 = (const float*)d_in[12];

    int E  = in_sizes[3] / NB;              // 500000
    int Nn = in_sizes[0] / HID;             // 50000
    long long nscal = (long long)Nn * HID;

    // zero accumulation buffer
    cudaMemsetAsync(d_out, 0, (size_t)out_size * sizeof(float));

    int blocks = (E + 255) / 256;
    // L1: x @ w1 -> silu -> g_H  (both m)
    l1_kernel<<<blocks, 128>>>(elen, sw1, sb1, vw1, vb1, E);
    // L2: g_H @ w2 -> g_W  (both m)
    l2_kernel<<<blocks, 128>>>(sw2, sb2, vw2, vb2, E);
    // K2: warp-per-edge gather+weight+scatter
    scatter_kernel<<<(E + 7) / 8, 256>>>(
        scalar, vec, eidx, (float*)d_out, E, nscal);
}

// round 14
// speedup vs baseline: 1.0878x; 1.0878x over previous
#include <cuda_runtime.h>
#include <cuda_bf16.h>

#define HID 64
#define NB  32
#define EMAX 500000

typedef unsigned long long ull;

// ---------------- static scratch ----------------
__device__ float g_W[(size_t)EMAX * 128];   // per-edge weights: [e][m*64 + j]

// ---------------- packed fp32x2 helpers ----------------
__device__ __forceinline__ ull dup2(float a) {
    ull r; asm("mov.b64 %0,{%1,%1};" : "=l"(r) : "f"(a)); return r;
}
__device__ __forceinline__ ull pack2(float a, float b) {
    ull r; asm("mov.b64 %0,{%1,%2};" : "=l"(r) : "f"(a), "f"(b)); return r;
}
__device__ __forceinline__ void up2(ull v, float& a, float& b) {
    asm("mov.b64 {%0,%1},%2;" : "=f"(a), "=f"(b) : "l"(v));
}
__device__ __forceinline__ void fma2(ull& d, ull a, ull b) {
    asm("fma.rn.f32x2 %0,%1,%2,%0;" : "+l"(d) : "l"(a), "l"(b));
}
__device__ __forceinline__ void red4(float* p, float a, float b, float c, float d) {
    asm volatile("red.global.add.v4.f32 [%0],{%1,%2,%3,%4};"
                 :: "l"(p), "f"(a), "f"(b), "f"(c), "f"(d) : "memory");
}
__device__ __forceinline__ float silu_f(float y) {
    return __fdividef(y, 1.f + __expf(-y));
}

// ================= K1: per-edge MLP (one m per launch), h in registers =================
// smem: w1 (2048) + w2 (4096) + b1 (64) + b2 (64) = 6272 floats = 25 KB
__global__ void __launch_bounds__(128, 3) mlp_kernel(
    const float* __restrict__ elen,
    const float* __restrict__ w1g, const float* __restrict__ b1g,
    const float* __restrict__ w2g, const float* __restrict__ b2g,
    int E, int m)
{
    __shared__ float sw[NB * HID + HID * HID + 2 * HID];
    int t = threadIdx.x;

    // cooperative weight load
    {
        const float4* g1 = (const float4*)w1g;
        const float4* g2 = (const float4*)w2g;
        float4* d1 = (float4*)sw;
        float4* d2 = (float4*)(sw + NB * HID);
        #pragma unroll
        for (int i = 0; i < 4; i++) d1[i * 128 + t] = g1[i * 128 + t];
        #pragma unroll
        for (int i = 0; i < 8; i++) d2[i * 128 + t] = g2[i * 128 + t];
        if (t < HID) {
            sw[6144 + t] = b1g[t];
            sw[6208 + t] = b2g[t];
        }
    }
    __syncthreads();

    long long e = (long long)blockIdx.x * 128 + t;
    if (e >= E) return;
    const float* xrow = elen + e * NB;

    // ---- layer 1: h = silu(x @ w1 + b1), h kept in registers (32 packed) ----
    ull h[32];
    #pragma unroll 1
    for (int jt = 0; jt < 2; jt++) {
        int j0 = jt * 32;
        ull acc[16];
        {
            const ull* bp = (const ull*)(sw + 6144 + j0);
            #pragma unroll
            for (int q = 0; q < 16; q++) acc[q] = bp[q];
        }
        #pragma unroll 1
        for (int k0 = 0; k0 < NB; k0 += 4) {
            float4 xv = *(const float4*)(xrow + k0);
            float xs[4] = {xv.x, xv.y, xv.z, xv.w};
            #pragma unroll
            for (int s = 0; s < 4; s++) {
                ull xd = dup2(xs[s]);
                const ulonglong2* wp =
                    (const ulonglong2*)(sw + (k0 + s) * HID + j0);
                #pragma unroll
                for (int q = 0; q < 8; q++) {
                    ulonglong2 wv = wp[q];
                    fma2(acc[2 * q],     xd, wv.x);
                    fma2(acc[2 * q + 1], xd, wv.y);
                }
            }
        }
        #pragma unroll
        for (int q = 0; q < 16; q++) {
            float a, b; up2(acc[q], a, b);
            h[jt * 16 + q] = pack2(silu_f(a), silu_f(b));
        }
    }

    // ---- layer 2: w = h @ w2 + b2 ----
    #pragma unroll 1
    for (int jt = 0; jt < 2; jt++) {
        int j0 = jt * 32;
        ull acc[16];
        {
            const ull* bp = (const ull*)(sw + 6208 + j0);
            #pragma unroll
            for (int q = 0; q < 16; q++) acc[q] = bp[q];
        }
        #pragma unroll 1
        for (int kp = 0; kp < 32; kp += 2) {     // covers k = 2*kp .. 2*kp+3
            float h0, h1, h2, h3;
            up2(h[kp],     h0, h1);
            up2(h[kp + 1], h2, h3);
            float hs[4] = {h0, h1, h2, h3};
            #pragma unroll
            for (int s = 0; s < 4; s++) {
                ull hd = dup2(hs[s]);
                const ulonglong2* wp =
                    (const ulonglong2*)(sw + NB * HID + (2 * kp + s) * HID + j0);
                #pragma unroll
                for (int q = 0; q < 8; q++) {
                    ulonglong2 wv = wp[q];
                    fma2(acc[2 * q],     hd, wv.x);
                    fma2(acc[2 * q + 1], hd, wv.y);
                }
            }
        }
        float4* o = (float4*)(g_W + (size_t)e * 128 + m * 64 + j0);
        #pragma unroll
        for (int i = 0; i < 8; i++) {
            float a, b, c, d;
            up2(acc[2 * i], a, b);
            up2(acc[2 * i + 1], c, d);
            o[i] = make_float4(a, b, c, d);
        }
    }
}

// ================= K2: one warp per edge, coalesced gather + red4 scatter =================
__global__ void __launch_bounds__(256) scatter_kernel(
    const float* __restrict__ scalar, const float* __restrict__ vec,
    const int* __restrict__ eidx,
    float* __restrict__ out, int E, long long nscal)
{
    long long e = (long long)blockIdx.x * 8 + (threadIdx.x >> 5);
    if (e >= E) return;
    int lane = threadIdx.x & 31;
    int seg = lane >> 3;               // 0: scalar, 1..3: vector dim
    int j = (lane * 8) & 63;           // 8-column group within seg

    int row = eidx[e];
    int col = eidx[E + e];

    const float* w = g_W + (size_t)e * 128 + (seg ? 64 : 0) + j;
    const float* s = (seg == 0)
        ? scalar + (size_t)col * HID + j
        : vec + (size_t)col * 3 * HID + (seg - 1) * HID + j;
    float* dst = (seg == 0)
        ? out + (size_t)row * HID + j
        : out + nscal + (size_t)row * 3 * HID + (seg - 1) * HID + j;

    float4 w0 = *(const float4*)w;
    float4 w1 = *(const float4*)(w + 4);
    float4 s0 = *(const float4*)s;
    float4 s1 = *(const float4*)(s + 4);

    red4(dst,     s0.x * w0.x, s0.y * w0.y, s0.z * w0.z, s0.w * w0.w);
    red4(dst + 4, s1.x * w1.x, s1.y * w1.y, s1.z * w1.z, s1.w * w1.w);
}

// ================= launch =================
extern "C" void kernel_launch(void* const* d_in, const int* in_sizes, int n_in,
                              void* d_out, int out_size)
{
    const float* scalar = (const float*)d_in[0];
    const float* vec    = (const float*)d_in[1];
    // d_in[2] = edge_sh (unused)
    const float* elen   = (const float*)d_in[3];
    const int*   eidx   = (const int*)d_in[4];
    const float* sw1 = (const float*)d_in[5];
    const float* sb1 = (const float*)d_in[6];
    const float* sw2 = (const float*)d_in[7];
    const float* sb2 = (const float*)d_in[8];
    const float* vw1 = (const float*)d_in[9];
    const float* vb1 = (const float*)d_in[10];
    const float* vw2 = (const float*)d_in[11];
    const float* vb2 = (const float*)d_in[12];

    int E  = in_sizes[3] / NB;              // 500000
    int Nn = in_sizes[0] / HID;             // 50000
    long long nscal = (long long)Nn * HID;

    // zero accumulation buffer
    cudaMemsetAsync(d_out, 0, (size_t)out_size * sizeof(float));

    int blocks = (E + 127) / 128;
    // K1a: scalar MLP (m = 0)
    mlp_kernel<<<blocks, 128>>>(elen, sw1, sb1, sw2, sb2, E, 0);
    // K1b: vector MLP (m = 1)
    mlp_kernel<<<blocks, 128>>>(elen, vw1, vb1, vw2, vb2, E, 1);
    // K2: warp-per-edge gather+weight+scatter
    scatter_kernel<<<(E + 7) / 8, 256>>>(
        scalar, vec, eidx, (float*)d_out, E, nscal);
}

// round 16
// speedup vs baseline: 1.1972x; 1.1006x over previous
#include <cuda_runtime.h>
#include <cuda_fp16.h>

#define HID 64
#define NB  32
#define EMAX 500000

typedef unsigned long long ull;

// ---------------- static scratch ----------------
__device__ float g_W[(size_t)EMAX * 128];   // per-edge weights: [e][m*64 + j]

// ---------------- packed fp32x2 helpers ----------------
__device__ __forceinline__ ull dup2(float a) {
    ull r; asm("mov.b64 %0,{%1,%1};" : "=l"(r) : "f"(a)); return r;
}
__device__ __forceinline__ void up2(ull v, float& a, float& b) {
    asm("mov.b64 {%0,%1},%2;" : "=f"(a), "=f"(b) : "l"(v));
}
__device__ __forceinline__ void fma2(ull& d, ull a, ull b) {
    asm("fma.rn.f32x2 %0,%1,%2,%0;" : "+l"(d) : "l"(a), "l"(b));
}
__device__ __forceinline__ void red4(float* p, float a, float b, float c, float d) {
    asm volatile("red.global.add.v4.f32 [%0],{%1,%2,%3,%4};"
                 :: "l"(p), "f"(a), "f"(b), "f"(c), "f"(d) : "memory");
}
__device__ __forceinline__ float silu_f(float y) {
    return __fdividef(y, 1.f + __expf(-y));
}

// ================= K1: per-edge MLP (one m per launch) =================
// thread tile: 4 edges x 16 cols.  block: 256 threads = 256 edges.
// smem floats: w1 [0,2048) | w2 [2048,6144) | b1 [6144,6208) | b2 [6208,6272)
// then fp16 h: 64 cols x 256 edge-slots (32 KB).  total 57856 B.
#define K1_SMEM (6272 * 4 + HID * 256 * 2)

__global__ void __launch_bounds__(256, 2) mlp_kernel(
    const float* __restrict__ elen,
    const float* __restrict__ w1g, const float* __restrict__ b1g,
    const float* __restrict__ w2g, const float* __restrict__ b2g,
    int E, int m)
{
    extern __shared__ float sm[];
    __half* hsm = (__half*)(sm + 6272);
    int t = threadIdx.x;

    // cooperative weight load
    {
        const float4* g1 = (const float4*)w1g;
        const float4* g2 = (const float4*)w2g;
        float4* d1 = (float4*)sm;
        float4* d2 = (float4*)(sm + 2048);
        d1[t] = g1[t];
        d1[256 + t] = g1[256 + t];
        #pragma unroll
        for (int i = 0; i < 4; i++) d2[i * 256 + t] = g2[i * 256 + t];
        if (t < HID) {
            sm[6144 + t] = b1g[t];
            sm[6208 + t] = b2g[t];
        }
    }
    __syncthreads();

    int eg = t >> 2;            // edge group 0..63
    int jt = t & 3;             // col tile 0..3 (16 cols each)
    int j0 = jt * 16;
    long long ebase = (long long)blockIdx.x * 256 + eg * 4;

    // clamped x row pointers (stores are predicated; loads just need valid addr)
    const float* xp[4];
    #pragma unroll
    for (int i = 0; i < 4; i++) {
        long long ec = ebase + i; if (ec >= E) ec = E - 1;
        xp[i] = elen + ec * NB;
    }

    // ---- layer 1: acc[4 edges][8 ull = 16 cols] ----
    ull a[32];
    {
        const ull* bp = (const ull*)(sm + 6144 + j0);
        #pragma unroll
        for (int q = 0; q < 8; q++) {
            ull b = bp[q];
            a[q] = b; a[8 + q] = b; a[16 + q] = b; a[24 + q] = b;
        }
    }
    #pragma unroll 1
    for (int k0 = 0; k0 < NB; k0 += 4) {
        float xk[4][4];
        #pragma unroll
        for (int i = 0; i < 4; i++) {
            float4 v = *(const float4*)(xp[i] + k0);
            xk[i][0] = v.x; xk[i][1] = v.y; xk[i][2] = v.z; xk[i][3] = v.w;
        }
        #pragma unroll
        for (int s = 0; s < 4; s++) {
            const ulonglong2* wp = (const ulonglong2*)(sm + (k0 + s) * HID + j0);
            ulonglong2 wa = wp[0], wb = wp[1], wc = wp[2], wd = wp[3];
            #pragma unroll
            for (int e = 0; e < 4; e++) {
                ull xd = dup2(xk[e][s]);
                fma2(a[e * 8 + 0], xd, wa.x); fma2(a[e * 8 + 1], xd, wa.y);
                fma2(a[e * 8 + 2], xd, wb.x); fma2(a[e * 8 + 3], xd, wb.y);
                fma2(a[e * 8 + 4], xd, wc.x); fma2(a[e * 8 + 5], xd, wc.y);
                fma2(a[e * 8 + 6], xd, wd.x); fma2(a[e * 8 + 7], xd, wd.y);
            }
        }
    }

    // ---- silu -> fp16 h staged [col][edge-slot] ----
    #pragma unroll
    for (int q = 0; q < 8; q++) {
        float l0, h0, l1, h1, l2, h2, l3, h3;
        up2(a[q],      l0, h0);
        up2(a[8 + q],  l1, h1);
        up2(a[16 + q], l2, h2);
        up2(a[24 + q], l3, h3);
        union { __half2 h2[2]; ull u; } plo, phi;
        plo.h2[0] = __floats2half2_rn(silu_f(l0), silu_f(l1));
        plo.h2[1] = __floats2half2_rn(silu_f(l2), silu_f(l3));
        phi.h2[0] = __floats2half2_rn(silu_f(h0), silu_f(h1));
        phi.h2[1] = __floats2half2_rn(silu_f(h2), silu_f(h3));
        *(ull*)(hsm + (j0 + 2 * q)     * 256 + eg * 4) = plo.u;
        *(ull*)(hsm + (j0 + 2 * q + 1) * 256 + eg * 4) = phi.u;
    }
    __syncthreads();

    // ---- layer 2: acc[4 edges][8 ull = 16 cols] over k = 0..63 ----
    ull A[32];
    {
        const ull* bp = (const ull*)(sm + 6208 + j0);
        #pragma unroll
        for (int q = 0; q < 8; q++) {
            ull b = bp[q];
            A[q] = b; A[8 + q] = b; A[16 + q] = b; A[24 + q] = b;
        }
    }
    #pragma unroll 4
    for (int k = 0; k < HID; k++) {
        union { ull u; __half2 h2[2]; } pk;
        pk.u = *(const ull*)(hsm + k * 256 + eg * 4);
        float2 f01 = __half22float2(pk.h2[0]);
        float2 f23 = __half22float2(pk.h2[1]);
        float hk[4] = {f01.x, f01.y, f23.x, f23.y};
        const ulonglong2* wp = (const ulonglong2*)(sm + 2048 + k * HID + j0);
        ulonglong2 wa = wp[0], wb = wp[1], wc = wp[2], wd = wp[3];
        #pragma unroll
        for (int e = 0; e < 4; e++) {
            ull hd = dup2(hk[e]);
            fma2(A[e * 8 + 0], hd, wa.x); fma2(A[e * 8 + 1], hd, wa.y);
            fma2(A[e * 8 + 2], hd, wb.x); fma2(A[e * 8 + 3], hd, wb.y);
            fma2(A[e * 8 + 4], hd, wc.x); fma2(A[e * 8 + 5], hd, wc.y);
            fma2(A[e * 8 + 6], hd, wd.x); fma2(A[e * 8 + 7], hd, wd.y);
        }
    }

    // ---- store 16 cols per edge to g_W ----
    #pragma unroll
    for (int e = 0; e < 4; e++) {
        if (ebase + e >= E) break;
        float4* o = (float4*)(g_W + (size_t)(ebase + e) * 128 + m * 64 + j0);
        #pragma unroll
        for (int i = 0; i < 4; i++) {
            float x, y, z, w;
            up2(A[e * 8 + 2 * i], x, y);
            up2(A[e * 8 + 2 * i + 1], z, w);
            o[i] = make_float4(x, y, z, w);
        }
    }
}

// ================= K2: one warp per edge, coalesced gather + red4 scatter =================
__global__ void __launch_bounds__(256) scatter_kernel(
    const float* __restrict__ scalar, const float* __restrict__ vec,
    const int* __restrict__ eidx,
    float* __restrict__ out, int E, long long nscal)
{
    long long e = (long long)blockIdx.x * 8 + (threadIdx.x >> 5);
    if (e >= E) return;
    int lane = threadIdx.x & 31;
    int seg = lane >> 3;               // 0: scalar, 1..3: vector dim
    int j = (lane * 8) & 63;           // 8-column group within seg

    int row = eidx[e];
    int col = eidx[E + e];

    const float* w = g_W + (size_t)e * 128 + (seg ? 64 : 0) + j;
    const float* s = (seg == 0)
        ? scalar + (size_t)col * HID + j
        : vec + (size_t)col * 3 * HID + (seg - 1) * HID + j;
    float* dst = (seg == 0)
        ? out + (size_t)row * HID + j
        : out + nscal + (size_t)row * 3 * HID + (seg - 1) * HID + j;

    float4 w0 = *(const float4*)w;
    float4 w1 = *(const float4*)(w + 4);
    float4 s0 = *(const float4*)s;
    float4 s1 = *(const float4*)(s + 4);

    red4(dst,     s0.x * w0.x, s0.y * w0.y, s0.z * w0.z, s0.w * w0.w);
    red4(dst + 4, s1.x * w1.x, s1.y * w1.y, s1.z * w1.z, s1.w * w1.w);
}

// ================= launch =================
extern "C" void kernel_launch(void* const* d_in, const int* in_sizes, int n_in,
                              void* d_out, int out_size)
{
    const float* scalar = (const float*)d_in[0];
    const float* vec    = (const float*)d_in[1];
    // d_in[2] = edge_sh (unused)
    const float* elen   = (const float*)d_in[3];
    const int*   eidx   = (const int*)d_in[4];
    const float* sw1 = (const float*)d_in[5];
    const float* sb1 = (const float*)d_in[6];
    const float* sw2 = (const float*)d_in[7];
    const float* sb2 = (const float*)d_in[8];
    const float* vw1 = (const float*)d_in[9];
    const float* vb1 = (const float*)d_in[10];
    const float* vw2 = (const float*)d_in[11];
    const float* vb2 = (const float*)d_in[12];

    int E  = in_sizes[3] / NB;              // 500000
    int Nn = in_sizes[0] / HID;             // 50000
    long long nscal = (long long)Nn * HID;

    // zero accumulation buffer
    cudaMemsetAsync(d_out, 0, (size_t)out_size * sizeof(float));

    cudaFuncSetAttribute(mlp_kernel,
                         cudaFuncAttributeMaxDynamicSharedMemorySize, K1_SMEM);

    int blocks = (E + 255) / 256;
    // K1a: scalar MLP (m = 0) — lands on ncu -s 5
    mlp_kernel<<<blocks, 256, K1_SMEM>>>(elen, sw1, sb1, sw2, sb2, E, 0);
    // K1b: vector MLP (m = 1)
    mlp_kernel<<<blocks, 256, K1_SMEM>>>(elen, vw1, vb1, vw2, vb2, E, 1);
    // K2: warp-per-edge gather+weight+scatter
    scatter_kernel<<<(E + 7) / 8, 256>>>(
        scalar, vec, eidx, (float*)d_out, E, nscal);
}